// round 12
// baseline (speedup 1.0000x reference)
#include <cuda_runtime.h>
#include <cuda_fp16.h>
#include <stdint.h>

// out[r,o] = tanh(scale(r) * dot(enc_row(r), W[o,:]) + b[o])
//   r = b*128 + m (m = l*4+n, l<32) -> M=4096 ; enc phys row = b*2048 + m
//   K=256, N=256. (Spectral DCT/mask/IDCT collapses to mask*enc since the
//   band mask is independent of the DCT index.)
//
// fp16 HMMA m16n8k16: A single fp16 (err 2^-12), B split hi+lo:
// D = A*Bh + A*Bl, fp32 accum -> rel err ~2.2e-4 (measured).
//
// Round 12: R11's K-chunk register-staged pipeline (4 chunks of 64,
// LDG(c+1) in flight under MMA(c)) + 512 threads = 16 warps (R11 had 8 ->
// occ 12%, latency-bound). Warp grid 4(M:32) x 4(N:16): 4 ldmx4 + 8 HMMA
// per k16. smem 128KB (A 64 + Bh 32 + Bl 32), grid (32,4) = 1 wave.

#define THREADS 512
#define OFF_A  0
#define OFF_BH 65536
#define OFF_BL 98304
#define DYN_SMEM 131072

static __device__ __forceinline__ uint32_t smem_u32(const void* p) {
    uint32_t a;
    asm("{ .reg .u64 t; cvta.to.shared.u64 t, %1; cvt.u32.u64 %0, t; }"
        : "=r"(a) : "l"(p));
    return a;
}

static __device__ __forceinline__ void ldmx4(uint32_t* r, uint32_t addr) {
    asm volatile("ldmatrix.sync.aligned.m8n8.x4.shared.b16 {%0,%1,%2,%3}, [%4];"
                 : "=r"(r[0]), "=r"(r[1]), "=r"(r[2]), "=r"(r[3]) : "r"(addr));
}

static __device__ __forceinline__ void mma16816(float* c, const uint32_t* a,
                                                uint32_t b0, uint32_t b1) {
    asm volatile(
        "mma.sync.aligned.m16n8k16.row.col.f32.f16.f16.f32 "
        "{%0,%1,%2,%3},{%4,%5,%6,%7},{%8,%9},{%0,%1,%2,%3};"
        : "+f"(c[0]), "+f"(c[1]), "+f"(c[2]), "+f"(c[3])
        : "r"(a[0]), "r"(a[1]), "r"(a[2]), "r"(a[3]), "r"(b0), "r"(b1));
}

static __device__ __forceinline__ float tanh_fast(float x) {
    float e = __expf(2.0f * x);
    return 1.0f - __fdividef(2.0f, e + 1.0f);
}

static __device__ __forceinline__ uint4 cvt8_h(const float4& v0, const float4& v1) {
    __half2 h0 = __floats2half2_rn(v0.x, v0.y);
    __half2 h1 = __floats2half2_rn(v0.z, v0.w);
    __half2 h2 = __floats2half2_rn(v1.x, v1.y);
    __half2 h3 = __floats2half2_rn(v1.z, v1.w);
    return make_uint4(*(uint32_t*)&h0, *(uint32_t*)&h1,
                      *(uint32_t*)&h2, *(uint32_t*)&h3);
}

__global__ __launch_bounds__(THREADS, 1) void spectral_hmma_kernel(
    const float* __restrict__ enc,
    const float* __restrict__ W,
    const float* __restrict__ bias,
    float* __restrict__ out)
{
    extern __shared__ __align__(16) uint8_t dyn[];
    const uint32_t sbase = smem_u32(dyn);

    const int tid = threadIdx.x;
    const int wid = tid >> 5;
    const int lid = tid & 31;
    const int bx = blockIdx.x;   // batch (M=128 rows), 0..31
    const int by = blockIdx.y;   // N tile (64 cols), 0..3

    const float4* __restrict__ encv = (const float4*)enc;
    const float4* __restrict__ Wv   = (const float4*)W;

    // per-thread chunk-load geometry: A chunk = 1024 32B-units, B = 512
    int aRowL[2], aCkl[2];
    #pragma unroll
    for (int s = 0; s < 2; ++s) {
        int g = tid + s * 512;          // 0..1023
        aRowL[s] = g >> 3;              // 0..127
        aCkl[s]  = g & 7;
    }
    const int bRowL = tid >> 3;         // 0..63  (tid < 512 -> 1 unit each)
    const int bCkl  = tid & 7;

    float4 sa[2][2], sb[2];

    auto prefetch = [&](int c) {
        #pragma unroll
        for (int s = 0; s < 2; ++s) {
            const float4* p = encv
                + ((size_t)(bx * 2048 + aRowL[s])) * 64 + (c * 8 + aCkl[s]) * 2;
            sa[s][0] = p[0]; sa[s][1] = p[1];
        }
        const float4* p = Wv
            + ((size_t)(by * 64 + bRowL)) * 64 + (c * 8 + bCkl) * 2;
        sb[0] = p[0]; sb[1] = p[1];
    };

    auto commit = [&](int c) {
        #pragma unroll
        for (int s = 0; s < 2; ++s) {
            int row = aRowL[s], ck = c * 8 + aCkl[s];
            uint32_t sw = row * 512 + (((ck ^ (row & 7)) & 31) << 4);
            *(uint4*)(dyn + OFF_A + sw) = cvt8_h(sa[s][0], sa[s][1]);
        }
        {
            int row = bRowL, ck = c * 8 + bCkl;
            float vs[8] = {sb[0].x, sb[0].y, sb[0].z, sb[0].w,
                           sb[1].x, sb[1].y, sb[1].z, sb[1].w};
            uint4 h, l;
            uint32_t* hp = (uint32_t*)&h;
            uint32_t* lp = (uint32_t*)&l;
            #pragma unroll
            for (int j = 0; j < 4; ++j) {
                __half2 hh = __floats2half2_rn(vs[j * 2], vs[j * 2 + 1]);
                float rx = vs[j * 2]     - __half2float(__low2half(hh));
                float ry = vs[j * 2 + 1] - __half2float(__high2half(hh));
                __half2 ll = __floats2half2_rn(rx, ry);
                hp[j] = *(uint32_t*)&hh;
                lp[j] = *(uint32_t*)&ll;
            }
            uint32_t sw = row * 512 + (((ck ^ (row & 7)) & 31) << 4);
            *(uint4*)(dyn + OFF_BH + sw) = h;
            *(uint4*)(dyn + OFF_BL + sw) = l;
        }
    };

    // ---- warp tiling: 16 warps = 4(M: 32 rows) x 4(N: 16 cols)
    const int wm = wid >> 2;
    const int wn = wid & 3;
    const int rl = lid & 15;
    const int kadd = lid >> 4;

    const int aR0 = wm * 32 + rl, aR1 = aR0 + 16;
    const uint32_t aO0 = aR0 * 512, aO1 = aR1 * 512;
    const int ax0 = aR0 & 7, ax1 = aR1 & 7;
    const int bR = wn * 16 + rl;
    const uint32_t bO = bR * 512;
    const int bxr = bR & 7;

    float acc[2][2][4];
    #pragma unroll
    for (int i = 0; i < 2; ++i)
        #pragma unroll
        for (int j = 0; j < 2; ++j)
            #pragma unroll
            for (int q = 0; q < 4; ++q)
                acc[i][j][q] = 0.f;

    // ---- pipelined mainloop over 4 K-chunks
    prefetch(0);
    commit(0);
    __syncthreads();

    for (int c = 0; c < 4; ++c) {
        if (c < 3) prefetch(c + 1);   // LDGs in flight under this chunk's MMA

        #pragma unroll
        for (int i = 0; i < 4; ++i) {
            const int ch = (c * 4 + i) * 2 + kadd;
            uint32_t a0[4], a1[4], bh[4], bl[4];
            ldmx4(a0, sbase + OFF_A  + aO0 + (((ch ^ ax0) & 31) << 4));
            ldmx4(a1, sbase + OFF_A  + aO1 + (((ch ^ ax1) & 31) << 4));
            ldmx4(bh, sbase + OFF_BH + bO  + (((ch ^ bxr) & 31) << 4));
            ldmx4(bl, sbase + OFF_BL + bO  + (((ch ^ bxr) & 31) << 4));
            mma16816(acc[0][0], a0, bh[0], bh[2]);
            mma16816(acc[0][1], a0, bh[1], bh[3]);
            mma16816(acc[1][0], a1, bh[0], bh[2]);
            mma16816(acc[1][1], a1, bh[1], bh[3]);
            mma16816(acc[0][0], a0, bl[0], bl[2]);
            mma16816(acc[0][1], a0, bl[1], bl[3]);
            mma16816(acc[1][0], a1, bl[0], bl[2]);
            mma16816(acc[1][1], a1, bl[1], bl[3]);
        }

        if (c < 3) {
            commit(c + 1);
            __syncthreads();
        }
    }

    // ---- epilogue: band scale, bias, tanh, store
    const int qr = lid >> 2;
    const int qc = (lid & 3) * 2;
    #pragma unroll
    for (int mt = 0; mt < 2; ++mt) {
        #pragma unroll
        for (int h = 0; h < 2; ++h) {
            const int m = wm * 32 + mt * 16 + h * 8 + qr;   // 0..127
            const int n = m & 3, ls = m >> 2;
            const float scale = (n == 0) ? 1.0f
                              : (n == 1) ? ((ls < 16) ? 0.1f : 1.0f)
                              : 0.1f;
            float* orow = out + ((size_t)(bx * 128 + m)) * 256
                              + by * 64 + wn * 16 + qc;
            const float* brow = bias + by * 64 + wn * 16 + qc;
            #pragma unroll
            for (int nt = 0; nt < 2; ++nt) {
                float2 bb = *(const float2*)(brow + nt * 8);
                float2 o;
                o.x = tanh_fast(fmaf(scale, acc[mt][nt][h * 2 + 0], bb.x));
                o.y = tanh_fast(fmaf(scale, acc[mt][nt][h * 2 + 1], bb.y));
                *(float2*)(orow + nt * 8) = o;
            }
        }
    }
}

extern "C" void kernel_launch(void* const* d_in, const int* in_sizes, int n_in,
                              void* d_out, int out_size) {
    const float* enc  = (const float*)d_in[0];
    const float* W    = (const float*)d_in[1];
    const float* bias = (const float*)d_in[2];
    float* out = (float*)d_out;

    cudaFuncSetAttribute(spectral_hmma_kernel,
                         cudaFuncAttributeMaxDynamicSharedMemorySize, DYN_SMEM);
    dim3 grid(32, 4);
    spectral_hmma_kernel<<<grid, THREADS, DYN_SMEM>>>(enc, W, bias, out);
}